// round 2
// baseline (speedup 1.0000x reference)
#include <cuda_runtime.h>
#include <math.h>

// ---------------- problem constants ----------------
#define BATCH   32
#define LSEQ    16
#define BL      512
#define M1      25088        // BL * 49
#define C1      576
#define K1      768
#define DCNN    64
#define K2      5184         // 576*9
#define DRNN    256
#define G3      768
#define HORIZON 10

typedef unsigned long long u64;

__device__ __forceinline__ void ffma2(u64 &c, u64 a, u64 b) {
    asm("fma.rn.f32x2 %0, %1, %2, %0;" : "+l"(c) : "l"(a), "l"(b));
}
__device__ __forceinline__ u64 dup2(float v) {
    u64 r; asm("mov.b64 %0, {%1,%2};" : "=l"(r) : "f"(v), "f"(v)); return r;
}
__device__ __forceinline__ float2 unpack2(u64 v) {
    float2 f; asm("mov.b64 {%0,%1}, %2;" : "=f"(f.x), "=f"(f.y) : "l"(v)); return f;
}

// ---------------- scratch ----------------
__device__ float g_f1p[BL * 81 * C1];   // conv1 out, padded 9x9 halo, channels-last (~95MB)
__device__ float g_y[M1 * DCNN];        // conv2 out (n,p,64)
__device__ float g_w2t[DCNN * K2];      // cnn1_w transposed [oc][tap*576+ic]
__device__ float g_pool[BL * DCNN];
__device__ float g_s[BL * DRNN];
__device__ float g_gi[BL * G3];
__device__ float g_wiht[DRNN * G3];
__device__ float g_whht[DRNN * G3];
__device__ float g_fit[DRNN * DRNN];
__device__ float g_h[BATCH * DRNN];

// ---------------- prep: weight transposes ----------------
__global__ void prep_kernel(const float* __restrict__ w_ih,
                            const float* __restrict__ w_hh,
                            const float* __restrict__ fi_w,
                            const float* __restrict__ cnn1_w)
{
    int i = blockIdx.x * blockDim.x + threadIdx.x;
    if (i < DRNN * G3) {
        int g = i / DRNN, k = i % DRNN;
        g_wiht[k * G3 + g] = w_ih[i];
        g_whht[k * G3 + g] = w_hh[i];
    }
    if (i < DRNN * DRNN) {
        int d = i / DRNN, k = i % DRNN;
        g_fit[k * DRNN + d] = fi_w[i];
    }
    if (i < DCNN * K2) {
        int oc = i / K2, r = i % K2;
        int tap = r / C1, ic = r % C1;
        g_w2t[i] = cnn1_w[oc * K2 + ic * 9 + tap];
    }
}

// ---------------- zero the 9x9 halo of g_f1p ----------------
__global__ void halo_zero_kernel()
{
    int i = blockIdx.x * blockDim.x + threadIdx.x;   // 512*32*576
    if (i >= BL * 32 * C1) return;
    int ic = i % C1;
    int t  = i / C1;
    int c  = t % 32;          // halo cell index
    int n  = t / 32;
    int yy, xx;
    if (c < 9)       { yy = 0;      xx = c; }
    else if (c < 18) { yy = 8;      xx = c - 9; }
    else if (c < 25) { yy = c - 17; xx = 0; }     // 1..7
    else             { yy = c - 24; xx = 8; }     // 1..7
    g_f1p[((size_t)n * 81 + yy * 9 + xx) * C1 + ic] = 0.f;
}

// ---------------- GEMM1: patchify conv ----------------
#define BM 128
#define BN 64
#define KT 16

__global__ __launch_bounds__(256) void gemm1_kernel(
    const float* __restrict__ frames,
    const float* __restrict__ w1,
    const float* __restrict__ b1)
{
    __shared__ __align__(16) float As[KT][BM + 4];
    __shared__ __align__(16) float Bs[KT][BN + 4];

    int tid = threadIdx.x;
    int kk = tid & 15;
    int ib = tid >> 4;
    int tx = tid & 15;
    int ty = tid >> 4;
    int rowBase = blockIdx.x * BM;
    int colBase = blockIdx.y * BN;

    const float* abase[8];
#pragma unroll
    for (int e = 0; e < 8; e++) {
        int m  = rowBase + ib + e * 16;
        int n  = m / 49;
        int p  = m - n * 49;
        int py = p / 7, px = p - py * 7;
        abase[e] = frames + n * 37632 + py * 1792 + px * 16;
    }

    u64 acc2[4][4];
#pragma unroll
    for (int i = 0; i < 4; i++)
#pragma unroll
        for (int j = 0; j < 4; j++) acc2[i][j] = 0ull;

    for (int k0 = 0; k0 < K1; k0 += KT) {
        int k   = k0 + kk;
        int c   = k >> 8;
        int rem = k & 255;
        int aoff = c * 12544 + (rem >> 4) * 112 + (rem & 15);
#pragma unroll
        for (int e = 0; e < 8; e++)
            As[kk][ib + e * 16] = abase[e][aoff];
#pragma unroll
        for (int e = 0; e < 4; e++) {
            int j = ib + e * 16;
            Bs[kk][j] = w1[(colBase + j) * K1 + k];
        }
        __syncthreads();
#pragma unroll
        for (int q = 0; q < KT; q++) {
            ulonglong2 A0 = *(const ulonglong2*)&As[q][ty * 8];
            ulonglong2 A1 = *(const ulonglong2*)&As[q][ty * 8 + 4];
            float4 b4 = *(const float4*)&Bs[q][tx * 4];
            u64 ap[4] = {A0.x, A0.y, A1.x, A1.y};
            u64 bd[4] = {dup2(b4.x), dup2(b4.y), dup2(b4.z), dup2(b4.w)};
#pragma unroll
            for (int i = 0; i < 4; i++)
#pragma unroll
                for (int j = 0; j < 4; j++) ffma2(acc2[i][j], ap[i], bd[j]);
        }
        __syncthreads();
    }

    float bias[4];
#pragma unroll
    for (int j = 0; j < 4; j++) bias[j] = b1[colBase + tx * 4 + j];

#pragma unroll
    for (int i2 = 0; i2 < 4; i2++) {
        int m0 = rowBase + ty * 8 + 2 * i2;
#pragma unroll
        for (int rr = 0; rr < 2; rr++) {
            int m = m0 + rr;
            int n = m / 49;
            int p = m - n * 49;
            int py = p / 7, px = p - py * 7;
            float* o = g_f1p + ((size_t)n * 81 + (1 + py) * 9 + (1 + px)) * C1
                             + colBase + tx * 4;
#pragma unroll
            for (int j = 0; j < 4; j++) {
                float2 v = unpack2(acc2[i2][j]);
                o[j] = (rr == 0 ? v.x : v.y) + bias[j];
            }
        }
    }
}

// ---------------- GEMM2: conv3x3 576->64 over padded input ----------------
__global__ __launch_bounds__(256) void gemm2_kernel(const float* __restrict__ b2)
{
    __shared__ __align__(16) float As[KT][BM + 4];
    __shared__ __align__(16) float Bs[KT][BN + 4];

    int tid = threadIdx.x;
    int kk = tid & 15;
    int ib = tid >> 4;
    int tx = tid & 15;
    int ty = tid >> 4;
    int rowBase = blockIdx.x * BM;

    const float* abase[8];
#pragma unroll
    for (int e = 0; e < 8; e++) {
        int m = rowBase + ib + e * 16;
        int n = m / 49;
        int p = m - n * 49;
        int py = p / 7, px = p - py * 7;
        abase[e] = g_f1p + ((size_t)n * 81 + (1 + py) * 9 + (1 + px)) * C1;
    }

    u64 acc2[4][4];
#pragma unroll
    for (int i = 0; i < 4; i++)
#pragma unroll
        for (int j = 0; j < 4; j++) acc2[i][j] = 0ull;

    for (int k0 = 0; k0 < K2; k0 += KT) {
        int tap = k0 / C1;                    // constant across the 16-chunk
        int ic  = k0 - tap * C1 + kk;
        int dy  = tap / 3 - 1, dx = tap - (tap / 3) * 3 - 1;
        int aoff = dy * 5184 + dx * 576 + ic;
#pragma unroll
        for (int e = 0; e < 8; e++)
            As[kk][ib + e * 16] = abase[e][aoff];
#pragma unroll
        for (int e = 0; e < 4; e++) {
            int j = ib + e * 16;
            Bs[kk][j] = g_w2t[j * K2 + k0 + kk];
        }
        __syncthreads();
#pragma unroll
        for (int q = 0; q < KT; q++) {
            ulonglong2 A0 = *(const ulonglong2*)&As[q][ty * 8];
            ulonglong2 A1 = *(const ulonglong2*)&As[q][ty * 8 + 4];
            float4 b4 = *(const float4*)&Bs[q][tx * 4];
            u64 ap[4] = {A0.x, A0.y, A1.x, A1.y};
            u64 bd[4] = {dup2(b4.x), dup2(b4.y), dup2(b4.z), dup2(b4.w)};
#pragma unroll
            for (int i = 0; i < 4; i++)
#pragma unroll
                for (int j = 0; j < 4; j++) ffma2(acc2[i][j], ap[i], bd[j]);
        }
        __syncthreads();
    }

    float bias[4];
#pragma unroll
    for (int j = 0; j < 4; j++) bias[j] = b2[tx * 4 + j];

#pragma unroll
    for (int i2 = 0; i2 < 4; i2++) {
        int m0 = rowBase + ty * 8 + 2 * i2;
#pragma unroll
        for (int rr = 0; rr < 2; rr++) {
            int m = m0 + rr;
            float* o = g_y + (size_t)m * DCNN + tx * 4;
#pragma unroll
            for (int j = 0; j < 4; j++) {
                float2 v = unpack2(acc2[i2][j]);
                o[j] = (rr == 0 ? v.x : v.y) + bias[j];
            }
        }
    }
}

// ---------------- relu + BN + mean-pool ----------------
__global__ void pool_kernel(const float* __restrict__ bn_g,
                            const float* __restrict__ bn_b,
                            const float* __restrict__ bn_m,
                            const float* __restrict__ bn_v)
{
    int n  = blockIdx.x;
    int oc = threadIdx.x;
    float s = 0.f;
    const float* base = g_y + (size_t)n * 49 * DCNN + oc;
#pragma unroll
    for (int p = 0; p < 49; p++) s += fmaxf(base[p * DCNN], 0.f);
    float inv = bn_g[oc] * rsqrtf(bn_v[oc] + 1e-5f);
    g_pool[n * DCNN + oc] = (s * (1.f / 49.f) - bn_m[oc]) * inv + bn_b[oc];
}

// ---------------- state adapters + concat + an ----------------
__global__ void adapter_kernel(const float* __restrict__ x,
                               const float* __restrict__ a0_w, const float* __restrict__ a0_b,
                               const float* __restrict__ ai_w, const float* __restrict__ ai_b,
                               const float* __restrict__ an_w, const float* __restrict__ an_b)
{
    int r = blockIdx.x;
    int tid = threadIdx.x;
    __shared__ float s0[16];
    __shared__ float cat[80];

    const float* xr = x + r * 12;
    if (tid < 16) {
        float a = a0_b[tid];
#pragma unroll
        for (int j = 0; j < 12; j++) a += xr[j] * a0_w[tid * 12 + j];
        s0[tid] = fmaxf(a, 0.f);
    }
    __syncthreads();
    if (tid < 16) {
        float a = ai_b[tid];
#pragma unroll
        for (int j = 0; j < 16; j++) a += s0[j] * ai_w[tid * 16 + j];
        cat[tid] = s0[tid] + fmaxf(a, 0.f);
    }
    if (tid >= 32 && tid < 96) cat[16 + tid - 32] = g_pool[r * DCNN + tid - 32];
    __syncthreads();

    float a = an_b[tid];
#pragma unroll
    for (int j = 0; j < 80; j++) a += cat[j] * an_w[tid * 80 + j];
    g_s[r * DRNN + tid] = fmaxf(a, 0.f);
}

// ---------------- encoder input gates, 16 rows per block ----------------
__global__ __launch_bounds__(256) void gi_kernel(const float* __restrict__ b_ih)
{
    int blk = blockIdx.x;       // 32 blocks, rows q = blk*16 .. +15
    int d = threadIdx.x;
    __shared__ __align__(16) float svT[DRNN][16];   // [k][row]

    for (int rr = 0; rr < 16; rr++) {
        int q = blk * 16 + rr;
        int t = q >> 5, b = q & 31;
        int r = b * 16 + t;
        svT[d][rr] = g_s[r * DRNN + d];
    }
    __syncthreads();

    float a0[16], a1[16], a2[16];
#pragma unroll
    for (int rr = 0; rr < 16; rr++) { a0[rr] = 0.f; a1[rr] = 0.f; a2[rr] = 0.f; }

    for (int k = 0; k < DRNN; k++) {
        const float* w = g_wiht + k * G3 + d;
        float w0 = w[0], w1 = w[256], w2 = w[512];
        const float4* s4 = (const float4*)&svT[k][0];
#pragma unroll
        for (int c = 0; c < 4; c++) {
            float4 sv = s4[c];
            float s[4] = {sv.x, sv.y, sv.z, sv.w};
#pragma unroll
            for (int u = 0; u < 4; u++) {
                int rr = c * 4 + u;
                a0[rr] += s[u] * w0;
                a1[rr] += s[u] * w1;
                a2[rr] += s[u] * w2;
            }
        }
    }

    float bi0 = b_ih[d], bi1 = b_ih[256 + d], bi2 = b_ih[512 + d];
#pragma unroll
    for (int rr = 0; rr < 16; rr++) {
        float* o = g_gi + (size_t)(blk * 16 + rr) * G3;
        o[d] = a0[rr] + bi0;
        o[256 + d] = a1[rr] + bi1;
        o[512 + d] = a2[rr] + bi2;
    }
}

__device__ __forceinline__ float sigmoidf_(float v) { return 1.f / (1.f + expf(-v)); }

// ---------------- fused encoder: 16 GRU steps per block ----------------
__global__ __launch_bounds__(256) void encoder_kernel(const float* __restrict__ b_hh)
{
    int b = blockIdx.x;
    int d = threadIdx.x;
    __shared__ float hs[DRNN];
    hs[d] = 0.f;
    __syncthreads();

    float bh0 = b_hh[d], bh1 = b_hh[256 + d], bh2 = b_hh[512 + d];

    for (int t = 0; t < LSEQ; t++) {
        float a0 = bh0, a1 = bh1, a2 = bh2;
#pragma unroll 4
        for (int k = 0; k < DRNN; k++) {
            float h = hs[k];
            const float* w = g_whht + k * G3 + d;
            a0 += h * w[0];
            a1 += h * w[256];
            a2 += h * w[512];
        }
        const float* gi = g_gi + (size_t)(t * 32 + b) * G3;
        float rr = sigmoidf_(gi[d] + a0);
        float zz = sigmoidf_(gi[256 + d] + a1);
        float nn = tanhf(gi[512 + d] + rr * a2);
        float newh = (1.f - zz) * nn + zz * hs[d];
        __syncthreads();
        hs[d] = newh;
        __syncthreads();
    }
    g_h[b * DRNN + d] = hs[d];
}

// ---------------- fused decoder: 10 steps, gru + residual + head ----------------
__global__ __launch_bounds__(256) void decoder_kernel(
    const float* __restrict__ b_ih, const float* __restrict__ b_hh,
    const float* __restrict__ fi_b,
    const float* __restrict__ fn_w, const float* __restrict__ fn_b,
    float* __restrict__ out)
{
    int b = blockIdx.x;
    int d = threadIdx.x;
    __shared__ float hs[DRNN];
    __shared__ float xs[DRNN];
    __shared__ float xr[DRNN];

    float h0 = g_h[b * DRNN + d];
    hs[d] = h0;
    xs[d] = h0;
    __syncthreads();

    float bh0 = b_hh[d], bh1 = b_hh[256 + d], bh2 = b_hh[512 + d];
    float bi0 = b_ih[d], bi1 = b_ih[256 + d], bi2 = b_ih[512 + d];
    float fib = fi_b[d];

    for (int t = 0; t < HORIZON; t++) {
        float a0 = bh0, a1 = bh1, a2 = bh2;
        float c0 = bi0, c1 = bi1, c2 = bi2;
#pragma unroll 4
        for (int k = 0; k < DRNN; k++) {
            float h = hs[k];
            float xv = xs[k];
            const float* wh = g_whht + k * G3 + d;
            const float* wi = g_wiht + k * G3 + d;
            a0 += h * wh[0];  a1 += h * wh[256];  a2 += h * wh[512];
            c0 += xv * wi[0]; c1 += xv * wi[256]; c2 += xv * wi[512];
        }
        float rr = sigmoidf_(c0 + a0);
        float zz = sigmoidf_(c1 + a1);
        float nn = tanhf(c2 + rr * a2);
        float newh = (1.f - zz) * nn + zz * hs[d];
        __syncthreads();
        hs[d] = newh;
        __syncthreads();

        // residual fi
        float a = fib;
#pragma unroll 4
        for (int k = 0; k < DRNN; k++) a += hs[k] * g_fit[k * DRNN + d];
        float v = hs[d] + fmaxf(a, 0.f);
        xr[d] = v;
        xs[d] = v;
        __syncthreads();

        if (d < 2) {
            float s = fn_b[d];
            for (int k = 0; k < DRNN; k++) s += xr[k] * fn_w[d * DRNN + k];
            out[(t * 32 + b) * 2 + d] = tanhf(s);
        }
        __syncthreads();
    }
}

// ---------------- launch ----------------
extern "C" void kernel_launch(void* const* d_in, const int* in_sizes, int n_in,
                              void* d_out, int out_size)
{
    const float* x      = (const float*)d_in[0];
    const float* frames = (const float*)d_in[1];
    const float* cnn_w  = (const float*)d_in[2];
    const float* cnn_b  = (const float*)d_in[3];
    const float* cnn1_w = (const float*)d_in[4];
    const float* cnn1_b = (const float*)d_in[5];
    const float* bn_g   = (const float*)d_in[6];
    const float* bn_b   = (const float*)d_in[7];
    const float* bn_m   = (const float*)d_in[8];
    const float* bn_v   = (const float*)d_in[9];
    const float* a0_w   = (const float*)d_in[10];
    const float* a0_b   = (const float*)d_in[11];
    const float* ai_w   = (const float*)d_in[12];
    const float* ai_b   = (const float*)d_in[13];
    const float* an_w   = (const float*)d_in[14];
    const float* an_b   = (const float*)d_in[15];
    const float* w_ih   = (const float*)d_in[16];
    const float* w_hh   = (const float*)d_in[17];
    const float* b_ih   = (const float*)d_in[18];
    const float* b_hh   = (const float*)d_in[19];
    const float* fi_w   = (const float*)d_in[20];
    const float* fi_b   = (const float*)d_in[21];
    const float* fn_w   = (const float*)d_in[22];
    const float* fn_b   = (const float*)d_in[23];
    float* out = (float*)d_out;

    prep_kernel<<<(DCNN * K2 + 255) / 256, 256>>>(w_ih, w_hh, fi_w, cnn1_w);
    halo_zero_kernel<<<(BL * 32 * C1 + 255) / 256, 256>>>();

    dim3 g1(M1 / BM, C1 / BN);
    gemm1_kernel<<<g1, 256>>>(frames, cnn_w, cnn_b);
    gemm2_kernel<<<M1 / BM, 256>>>(cnn1_b);

    pool_kernel<<<BL, DCNN>>>(bn_g, bn_b, bn_m, bn_v);
    adapter_kernel<<<BL, DRNN>>>(x, a0_w, a0_b, ai_w, ai_b, an_w, an_b);
    gi_kernel<<<BL / 16, DRNN>>>(b_ih);

    encoder_kernel<<<BATCH, DRNN>>>(b_hh);
    decoder_kernel<<<BATCH, DRNN>>>(b_ih, b_hh, fi_b, fn_w, fn_b, out);
}